// round 8
// baseline (speedup 1.0000x reference)
#include <cuda_runtime.h>
#include <cuda_bf16.h>
#include <math.h>
#include <float.h>
#include <stdint.h>

// ---------------- problem constants ----------------
#define Bsz   8
#define Npts  2048
#define Kn    16
#define Hc    128
#define Lc    4
#define CDc   128
#define Jtot  (Bsz * Npts * 3)
#define NBlk  (Bsz * Npts)
#define EPSf  1e-12f

typedef __nv_bfloat16 bf16;

// ---------------- scratch ----------------
__device__ int   g_idx[NBlk * Kn];
__device__ float g_M3[Hc * 3];
__device__ bf16  g_UKh[Lc * 256 * 128];
__device__ bf16  g_UKl[Lc * 256 * 128];
__device__ bf16  g_GWh[Lc * 256 * 256];
__device__ bf16  g_GWl[Lc * 256 * 256];
__device__ bf16  g_OWh[128 * 512];
__device__ bf16  g_OWl[128 * 512];
__device__ bf16  g_X0h[Jtot * 128];
__device__ bf16  g_X0l[Jtot * 128];
__device__ bf16  g_X2h[Jtot * 128];
__device__ bf16  g_X2l[Jtot * 128];
__device__ bf16  g_FTh[Jtot * 512];
__device__ bf16  g_FTl[Jtot * 512];
__device__ float g_C[Jtot * 256];
__device__ float g_gmean[Bsz * 3 * Hc];
__device__ float g_bias[24 * 256];

// ---------------- helpers ----------------
__device__ __forceinline__ void split2(float v, bf16& h, bf16& l) {
    h = __float2bfloat16(v);
    l = __float2bfloat16(v - __bfloat162float(h));
}

__device__ __forceinline__ uint32_t smem_u32(const void* p) {
    uint32_t r;
    asm("{ .reg .u64 t; cvta.to.shared.u64 t, %1; cvt.u32.u64 %0, t; }"
        : "=r"(r) : "l"(p));
    return r;
}

__device__ __forceinline__ void cpasync16(uint32_t dst, const void* src) {
    asm volatile("cp.async.cg.shared.global [%0], [%1], 16;" :: "r"(dst), "l"(src));
}
__device__ __forceinline__ void cpcommit() {
    asm volatile("cp.async.commit_group;" ::: "memory");
}
template <int N> __device__ __forceinline__ void cpwait() {
    asm volatile("cp.async.wait_group %0;" :: "n"(N) : "memory");
}

__device__ __forceinline__ void ldsm_x4(uint32_t& r0, uint32_t& r1,
                                        uint32_t& r2, uint32_t& r3, uint32_t addr) {
    asm volatile("ldmatrix.sync.aligned.m8n8.x4.shared.b16 {%0,%1,%2,%3}, [%4];"
                 : "=r"(r0), "=r"(r1), "=r"(r2), "=r"(r3) : "r"(addr));
}
__device__ __forceinline__ void ldsm_x2(uint32_t& r0, uint32_t& r1, uint32_t addr) {
    asm volatile("ldmatrix.sync.aligned.m8n8.x2.shared.b16 {%0,%1}, [%2];"
                 : "=r"(r0), "=r"(r1) : "r"(addr));
}
__device__ __forceinline__ void mma16816(float* d, const uint32_t* a, const uint32_t* b) {
    asm volatile("mma.sync.aligned.m16n8k16.row.col.f32.bf16.bf16.f32 "
                 "{%0,%1,%2,%3}, {%4,%5,%6,%7}, {%8,%9}, {%0,%1,%2,%3};"
                 : "+f"(d[0]), "+f"(d[1]), "+f"(d[2]), "+f"(d[3])
                 : "r"(a[0]), "r"(a[1]), "r"(a[2]), "r"(a[3]),
                   "r"(b[0]), "r"(b[1]));
}

// ---------------- prep: fused+stacked+split weights ----------------
__global__ void prep_kernel(const float* __restrict__ W_in,
                            const float* __restrict__ Wd_in,
                            const float* __restrict__ Ws,
                            const float* __restrict__ Wds,
                            const float* __restrict__ Gs,
                            const float* __restrict__ Gds,
                            const float* __restrict__ W_out) {
    int t = blockIdx.x * blockDim.x + threadIdx.x;
    const int N3  = Hc * 3;
    const int NUK = Lc * 256 * 128;
    const int NGW = Lc * 256 * 256;
    const int NOW = 128 * 512;
    if (t < N3) {
        int o = t / 3, i = t % 3;
        float s = 0.f;
        #pragma unroll 8
        for (int c = 0; c < Hc; c++) s += Wd_in[o * Hc + c] * W_in[c * 3 + i];
        g_M3[t] = s;
    } else if (t < N3 + NUK) {
        int r = t - N3;
        int l = r >> 15;
        int o = (r >> 7) & 255;
        int c = r & 127;
        float v;
        if (o < 128) {
            v = Ws[l * Hc * Hc + o * Hc + c];
        } else {
            const float* wd = Wds + l * Hc * Hc + (o - 128) * Hc;
            const float* w  = Ws  + l * Hc * Hc;
            float s = 0.f;
            #pragma unroll 8
            for (int cc = 0; cc < Hc; cc++) s += wd[cc] * w[cc * Hc + c];
            v = s;
        }
        split2(v, g_UKh[r], g_UKl[r]);
    } else if (t < N3 + NUK + NGW) {
        int r = t - N3 - NUK;
        int l = r >> 16;
        int o = (r >> 8) & 255;
        int c = r & 255;
        float v;
        if (o < 128) {
            v = Gs[l * Hc * 2 * Hc + o * 2 * Hc + c];
        } else {
            const float* gd = Gds + l * Hc * Hc + (o - 128) * Hc;
            const float* g  = Gs  + l * Hc * 2 * Hc;
            float s = 0.f;
            #pragma unroll 8
            for (int cc = 0; cc < Hc; cc++) s += gd[cc] * g[cc * 2 * Hc + c];
            v = s;
        }
        split2(v, g_GWh[r], g_GWl[r]);
    } else if (t < N3 + NUK + NGW + NOW) {
        int r = t - N3 - NUK - NGW;
        split2(W_out[r], g_OWh[r], g_OWl[r]);
    }
}

// ---------------- kNN ----------------
__global__ void knn_kernel(const float* __restrict__ x) {
    __shared__ float4 spts[Npts];
    int b = blockIdx.x >> 3;
    int chunk = blockIdx.x & 7;
    const float* xb = x + b * 3 * Npts;
    for (int i = threadIdx.x; i < Npts; i += 256) {
        float px = xb[i], py = xb[Npts + i], pz = xb[2 * Npts + i];
        spts[i] = make_float4(px, py, pz, px * px + py * py + pz * pz);
    }
    __syncthreads();
    int q = chunk * 256 + threadIdx.x;
    float4 Q = spts[q];
    float bd[Kn]; int bi[Kn];
    #pragma unroll
    for (int t = 0; t < Kn; t++) { bd[t] = FLT_MAX; bi[t] = 0; }
    float worst = FLT_MAX; int wslot = 0;
    for (int m = 0; m < Npts; m++) {
        float4 P = spts[m];
        float d2 = Q.w + P.w - 2.f * (Q.x * P.x + Q.y * P.y + Q.z * P.z);
        if (d2 < worst) {
            #pragma unroll
            for (int t = 0; t < Kn; t++) if (t == wslot) { bd[t] = d2; bi[t] = m; }
            worst = bd[0]; wslot = 0;
            #pragma unroll
            for (int t = 1; t < Kn; t++) if (bd[t] > worst) { worst = bd[t]; wslot = t; }
        }
    }
    int base = (b * Npts + q) * Kn;
    #pragma unroll
    for (int t = 0; t < Kn; t++) g_idx[base + t] = bi[t];
}

// ---------------- fused edge stage ----------------
__global__ void stage2_kernel(const float* __restrict__ x,
                              const float* __restrict__ W_in) {
    __shared__ float3 snbr[Kn];
    __shared__ float swk[4][Kn];
    int bn = blockIdx.x;
    int b = bn >> 11, n = bn & 2047;
    int c = threadIdx.x;
    int wid = c >> 5, lane = c & 31;
    const float* xb = x + b * 3 * Npts;
    float xnx = xb[n], xny = xb[Npts + n], xnz = xb[2 * Npts + n];
    float xl = sqrtf(xnx * xnx + xny * xny + xnz * xnz);
    float xinv = 1.f / fmaxf(xl, EPSf);
    float dxx = xnx * xinv, dxy = xny * xinv, dxz = xnz * xinv;
    if (c < Kn) {
        int m = g_idx[bn * Kn + c];
        snbr[c] = make_float3(xb[m], xb[Npts + m], xb[2 * Npts + m]);
    }
    __syncthreads();
    float w0 = W_in[c * 3 + 0], w1 = W_in[c * 3 + 1], w2 = W_in[c * 3 + 2];
    float m0 = g_M3[c * 3 + 0], m1 = g_M3[c * 3 + 1], m2 = g_M3[c * 3 + 2];
    float sumk[Kn];
    #pragma unroll
    for (int k = 0; k < Kn; k++) {
        float3 p = snbr[k];
        float c0x = dxy * p.z - dxz * p.y;
        float c0y = dxz * p.x - dxx * p.z;
        float c0z = dxx * p.y - dxy * p.x;
        float e1x = p.x - xnx, e1y = p.y - xny, e1z = p.z - xnz;
        float ux = w0 * c0x + w1 * e1x + w2 * xnx;
        float uy = w0 * c0y + w1 * e1y + w2 * xny;
        float uz = w0 * c0z + w1 * e1z + w2 * xnz;
        sumk[k] = ux * ux + uy * uy + uz * uz;
    }
    #pragma unroll
    for (int o = 16; o > 0; o >>= 1)
        #pragma unroll
        for (int k = 0; k < Kn; k++)
            sumk[k] += __shfl_xor_sync(0xffffffffu, sumk[k], o);
    if (lane == 0) {
        #pragma unroll
        for (int k = 0; k < Kn; k++) swk[wid][k] = sumk[k];
    }
    __syncthreads();
    float ax = 0.f, ay = 0.f, az = 0.f;
    #pragma unroll
    for (int k = 0; k < Kn; k++) {
        float tot = swk[0][k] + swk[1][k] + swk[2][k] + swk[3][k];
        float3 p = snbr[k];
        float c0x = dxy * p.z - dxz * p.y;
        float c0y = dxz * p.x - dxx * p.z;
        float c0z = dxx * p.y - dxy * p.x;
        float e1x = p.x - xnx, e1y = p.y - xny, e1z = p.z - xnz;
        float ux = w0 * c0x + w1 * e1x + w2 * xnx;
        float uy = w0 * c0y + w1 * e1y + w2 * xny;
        float uz = w0 * c0z + w1 * e1z + w2 * xnz;
        float kx = m0 * c0x + m1 * e1x + m2 * xnx;
        float ky = m0 * c0y + m1 * e1y + m2 * xny;
        float kz = m0 * c0z + m1 * e1z + m2 * xnz;
        float s = 1.f / fmaxf(sqrtf(tot), EPSf);
        float kl = sqrtf(kx * kx + ky * ky + kz * kz);
        float ki = 1.f / fmaxf(kl, EPSf);
        kx *= ki; ky *= ki; kz *= ki;
        float dot = s * (ux * kx + uy * ky + uz * kz);
        float neg = fminf(dot, 0.f);
        ax += s * ux - neg * kx;
        ay += s * uy - neg * ky;
        az += s * uz - neg * kz;
    }
    const float invK = 1.f / (float)Kn;
    int j0 = bn * 3;
    split2(ax * invK, g_X0h[(size_t)(j0 + 0) * Hc + c], g_X0l[(size_t)(j0 + 0) * Hc + c]);
    split2(ay * invK, g_X0h[(size_t)(j0 + 1) * Hc + c], g_X0l[(size_t)(j0 + 1) * Hc + c]);
    split2(az * invK, g_X0h[(size_t)(j0 + 2) * Hc + c], g_X0l[(size_t)(j0 + 2) * Hc + c]);
}

// ---------------- bf16x3 mma.sync GEMM: BM=128, BN=64, high occupancy ----------
// C[j][n] = sum_c A[j,c]*W[n,c] (+ bias); K' = 3*Cin, BK=32.
// 8 warps as warpM(2) x warpN(4); warp tile 64x16; acc 4x2x4 = 32 fp32.
__global__ __launch_bounds__(256, 3)
void gemm_bf16(const bf16* __restrict__ Ah, const bf16* __restrict__ Al, int lda, int Cin,
               const bf16* __restrict__ Wh, const bf16* __restrict__ Wl, int ldw,
               float* __restrict__ C, int ldc, const float* __restrict__ bias) {
    __shared__ __align__(16) bf16 As[2][128 * 40];
    __shared__ __align__(16) bf16 Bs[2][64 * 40];
    int tid = threadIdx.x, lane = tid & 31, wid = tid >> 5;
    int warpM = wid >> 2, warpN = wid & 3;
    int jBase = blockIdx.x * 128;
    int nBase = blockIdx.y * 64;
    float acc[4][2][4];
    #pragma unroll
    for (int mt = 0; mt < 4; mt++)
        #pragma unroll
        for (int nt = 0; nt < 2; nt++)
            #pragma unroll
            for (int e = 0; e < 4; e++) acc[mt][nt][e] = 0.f;

    const int nIter = (3 * Cin) >> 5;
    const int ar = tid >> 1;              // A row (0..127), 2 chunks each
    const int ac = (tid & 1) * 2;
    const int br = tid >> 2;              // B row (0..63), 1 chunk each
    const int bc = tid & 3;
    uint32_t sA0 = smem_u32(&As[0][0]);
    uint32_t sB0 = smem_u32(&Bs[0][0]);

    #define LOAD_SLAB(IT, BUF)                                                     \
    do {                                                                           \
        int k0 = (IT) << 5;                                                        \
        int seg = k0 / Cin;                                                        \
        int kin = k0 - seg * Cin;                                                  \
        const bf16* Ap = (seg == 1) ? Al : Ah;                                     \
        const bf16* Bp = (seg == 2) ? Wl : Wh;                                     \
        uint32_t adst = sA0 + (BUF) * 10240 + (ar * 40 + ac * 8) * 2;              \
        uint32_t bdst = sB0 + (BUF) * 5120  + (br * 40 + bc * 8) * 2;              \
        cpasync16(adst,      Ap + (size_t)(jBase + ar) * lda + kin + ac * 8);      \
        cpasync16(adst + 16, Ap + (size_t)(jBase + ar) * lda + kin + ac * 8 + 8);  \
        cpasync16(bdst,      Bp + (size_t)(nBase + br) * ldw + kin + bc * 8);      \
    } while (0)

    LOAD_SLAB(0, 0);
    cpcommit();
    cpwait<0>();
    __syncthreads();

    for (int it = 0; it < nIter; it++) {
        int cur = it & 1;
        if (it + 1 < nIter) {
            LOAD_SLAB(it + 1, cur ^ 1);
            cpcommit();
        }
        uint32_t sA = sA0 + cur * 10240;
        uint32_t sB = sB0 + cur * 5120;
        #pragma unroll
        for (int s = 0; s < 2; s++) {
            uint32_t afr[4][4];
            uint32_t bfr[2][2];
            #pragma unroll
            for (int mt = 0; mt < 4; mt++) {
                uint32_t addrA = sA + ((warpM * 64 + mt * 16 + (lane & 15)) * 40) * 2
                               + s * 32 + ((lane >> 4) << 4);
                ldsm_x4(afr[mt][0], afr[mt][1], afr[mt][2], afr[mt][3], addrA);
            }
            #pragma unroll
            for (int nt = 0; nt < 2; nt++) {
                uint32_t addrB = sB + ((warpN * 16 + nt * 8 + (lane & 7)) * 40) * 2
                               + s * 32 + (((lane >> 3) & 1) << 4);
                ldsm_x2(bfr[nt][0], bfr[nt][1], addrB);
            }
            #pragma unroll
            for (int mt = 0; mt < 4; mt++)
                #pragma unroll
                for (int nt = 0; nt < 2; nt++)
                    mma16816(acc[mt][nt], afr[mt], bfr[nt]);
        }
        if (it + 1 < nIter) {
            cpwait<0>();
            __syncthreads();
        }
    }
    #undef LOAD_SLAB

    #pragma unroll
    for (int mt = 0; mt < 4; mt++) {
        int m = jBase + warpM * 64 + mt * 16 + (lane >> 2);
        int bd0 = (m / 6144) * 3 + (m % 3);
        int m8 = m + 8;
        int bd1 = (m8 / 6144) * 3 + (m8 % 3);
        #pragma unroll
        for (int nt = 0; nt < 2; nt++) {
            int n = nBase + warpN * 16 + nt * 8 + (lane & 3) * 2;
            float b00 = 0.f, b01 = 0.f, b10 = 0.f, b11 = 0.f;
            if (bias) {
                b00 = bias[bd0 * 256 + n];     b01 = bias[bd0 * 256 + n + 1];
                b10 = bias[bd1 * 256 + n];     b11 = bias[bd1 * 256 + n + 1];
            }
            *(float2*)&C[(size_t)m * ldc + n] =
                make_float2(acc[mt][nt][0] + b00, acc[mt][nt][1] + b01);
            *(float2*)&C[(size_t)m8 * ldc + n] =
                make_float2(acc[mt][nt][2] + b10, acc[mt][nt][3] + b11);
        }
    }
}

// ---------------- vec_lna pointwise epilogue (2 bn per block) ----------------
__global__ __launch_bounds__(256)
void pointwise_kernel(const float* __restrict__ Cbuf,
                      bf16* __restrict__ dstH, bf16* __restrict__ dstL,
                      int ldd, int off) {
    __shared__ float sred[2][4];
    int half = threadIdx.x >> 7;
    int c = threadIdx.x & 127;
    int wih = (threadIdx.x >> 5) & 3;
    int lane = threadIdx.x & 31;
    int bn = blockIdx.x * 2 + half;
    int j0 = bn * 3;
    float ux = Cbuf[(size_t)(j0 + 0) * 256 + c];
    float uy = Cbuf[(size_t)(j0 + 1) * 256 + c];
    float uz = Cbuf[(size_t)(j0 + 2) * 256 + c];
    float kx = Cbuf[(size_t)(j0 + 0) * 256 + 128 + c];
    float ky = Cbuf[(size_t)(j0 + 1) * 256 + 128 + c];
    float kz = Cbuf[(size_t)(j0 + 2) * 256 + 128 + c];
    float v = ux * ux + uy * uy + uz * uz;
    #pragma unroll
    for (int o = 16; o > 0; o >>= 1) v += __shfl_xor_sync(0xffffffffu, v, o);
    if (lane == 0) sred[half][wih] = v;
    __syncthreads();
    float tot = sred[half][0] + sred[half][1] + sred[half][2] + sred[half][3];
    float s = 1.f / fmaxf(sqrtf(tot), EPSf);
    float kl = sqrtf(kx * kx + ky * ky + kz * kz);
    float ki = 1.f / fmaxf(kl, EPSf);
    kx *= ki; ky *= ki; kz *= ki;
    float dot = s * (ux * kx + uy * ky + uz * kz);
    float neg = fminf(dot, 0.f);
    split2(s * ux - neg * kx, dstH[(size_t)(j0 + 0) * ldd + off + c], dstL[(size_t)(j0 + 0) * ldd + off + c]);
    split2(s * uy - neg * ky, dstH[(size_t)(j0 + 1) * ldd + off + c], dstL[(size_t)(j0 + 1) * ldd + off + c]);
    split2(s * uz - neg * kz, dstH[(size_t)(j0 + 2) * ldd + off + c], dstL[(size_t)(j0 + 2) * ldd + off + c]);
}

// ---------------- fused mean-over-N + g-half bias ----------------
// block bd (24): gmean[bd] = sum_n h1; bias[bd][o] = dot(GW[o][128:256], gmean/N)
__global__ __launch_bounds__(1024)
void meanN_bias_kernel(const bf16* __restrict__ GWh, const bf16* __restrict__ GWl) {
    __shared__ float part[8][128];
    __shared__ float gm[128];
    int bd = blockIdx.x;
    int b = bd / 3, d = bd % 3;
    int c = threadIdx.x & 127;
    int slab = threadIdx.x >> 7;
    size_t base = ((size_t)(b * Npts + slab * 256) * 3 + d) * 128 + c;
    float s = 0.f;
    #pragma unroll 8
    for (int n = 0; n < 256; n++) {
        size_t a = base + (size_t)n * 384;
        s += __bfloat162float(g_X2h[a]) + __bfloat162float(g_X2l[a]);
    }
    part[slab][c] = s;
    __syncthreads();
    if (threadIdx.x < 128) {
        float t = 0.f;
        #pragma unroll
        for (int p = 0; p < 8; p++) t += part[p][c];
        g_gmean[bd * Hc + c] = t;
        gm[c] = t * (1.f / (float)Npts);
    }
    __syncthreads();
    if (threadIdx.x < 256) {
        int o = threadIdx.x;
        const bf16* rh = GWh + (size_t)o * 256 + 128;
        const bf16* rl = GWl + (size_t)o * 256 + 128;
        float acc = 0.f;
        #pragma unroll 8
        for (int cc = 0; cc < 128; cc++)
            acc += (__bfloat162float(rh[cc]) + __bfloat162float(rl[cc])) * gm[cc];
        g_bias[bd * 256 + o] = acc;
    }
}

// ---------------- coalesced tiled-transpose writeout ----------------
__global__ __launch_bounds__(256)
void writeout_kernel(float* __restrict__ out, int big_off) {
    __shared__ float tile[32][33];
    int tx = threadIdx.x & 31;
    int ty = threadIdx.x >> 5;
    int n0 = blockIdx.x * 32;
    int o0 = blockIdx.y * 32;
    int bd = blockIdx.z;
    int b = bd / 3, d = bd % 3;
    #pragma unroll
    for (int i = 0; i < 4; i++) {
        int n = n0 + ty + i * 8;
        tile[ty + i * 8][tx] = g_C[(((size_t)(b * Npts + n)) * 3 + d) * 128 + o0 + tx];
    }
    __syncthreads();
    #pragma unroll
    for (int i = 0; i < 4; i++) {
        int o = o0 + ty + i * 8;
        out[big_off + (((size_t)(b * 128 + o)) * 3 + d) * Npts + n0 + tx] = tile[tx][ty + i * 8];
    }
}

__global__ void meanout_kernel(float* __restrict__ out, int big_off, int mean_off) {
    int w = blockIdx.x * 8 + (threadIdx.x >> 5);
    int lane = threadIdx.x & 31;
    const float* base = out + big_off + (size_t)w * Npts;
    float s = 0.f;
    #pragma unroll 8
    for (int i = lane; i < Npts; i += 32) s += base[i];
    #pragma unroll
    for (int o = 16; o > 0; o >>= 1) s += __shfl_xor_sync(0xffffffffu, s, o);
    if (lane == 0) out[mean_off + w] = s * (1.f / (float)Npts);
}

// ---------------- host launcher ----------------
extern "C" void kernel_launch(void* const* d_in, const int* in_sizes, int n_in,
                              void* d_out, int out_size) {
    const float* x     = (const float*)d_in[0];
    const float* W_in  = (const float*)d_in[1];
    const float* Wd_in = (const float*)d_in[2];
    const float* Ws    = (const float*)d_in[3];
    const float* Wds   = (const float*)d_in[4];
    const float* Gs    = (const float*)d_in[5];
    const float* Gds   = (const float*)d_in[6];
    const float* W_out = (const float*)d_in[7];
    float* out = (float*)d_out;

    float *pC, *pBias;
    bf16 *pX0h, *pX0l, *pX2h, *pX2l, *pFTh, *pFTl, *pUKh, *pUKl, *pGWh, *pGWl, *pOWh, *pOWl;
    cudaGetSymbolAddress((void**)&pC, g_C);
    cudaGetSymbolAddress((void**)&pBias, g_bias);
    cudaGetSymbolAddress((void**)&pX0h, g_X0h);
    cudaGetSymbolAddress((void**)&pX0l, g_X0l);
    cudaGetSymbolAddress((void**)&pX2h, g_X2h);
    cudaGetSymbolAddress((void**)&pX2l, g_X2l);
    cudaGetSymbolAddress((void**)&pFTh, g_FTh);
    cudaGetSymbolAddress((void**)&pFTl, g_FTl);
    cudaGetSymbolAddress((void**)&pUKh, g_UKh);
    cudaGetSymbolAddress((void**)&pUKl, g_UKl);
    cudaGetSymbolAddress((void**)&pGWh, g_GWh);
    cudaGetSymbolAddress((void**)&pGWl, g_GWl);
    cudaGetSymbolAddress((void**)&pOWh, g_OWh);
    cudaGetSymbolAddress((void**)&pOWl, g_OWl);

    int mean_off = 0, big_off = 0;
    bool has_mean = true;
    const int BIG = Bsz * CDc * 3 * Npts;
    const int MEAN = Bsz * CDc * 3;
    if (out_size >= BIG + MEAN) { mean_off = 0; big_off = MEAN; }
    else { big_off = 0; has_mean = false; }

    const int prepTot = 384 + Lc * 256 * 128 + Lc * 256 * 256 + 128 * 512;
    prep_kernel<<<(prepTot + 255) / 256, 256>>>(W_in, Wd_in, Ws, Wds, Gs, Gds, W_out);
    knn_kernel<<<Bsz * 8, 256>>>(x);
    stage2_kernel<<<NBlk, 128>>>(x, W_in);

    const bf16* Xh = pX0h;
    const bf16* Xl = pX0l;
    int lda = Hc;
    dim3 g4(Jtot / 128, 4), g2(Jtot / 128, 2);
    for (int i = 0; i < Lc; i++) {
        gemm_bf16<<<g4, 256>>>(Xh, Xl, lda, 128,
                               pUKh + (size_t)i * 256 * 128, pUKl + (size_t)i * 256 * 128, 128,
                               pC, 256, nullptr);
        pointwise_kernel<<<NBlk / 2, 256>>>(pC, pX2h, pX2l, 128, 0);
        meanN_bias_kernel<<<24, 1024>>>(pGWh + (size_t)i * 256 * 256,
                                        pGWl + (size_t)i * 256 * 256);
        gemm_bf16<<<g4, 256>>>(pX2h, pX2l, 128, 128,
                               pGWh + (size_t)i * 256 * 256, pGWl + (size_t)i * 256 * 256, 256,
                               pC, 256, pBias);
        pointwise_kernel<<<NBlk / 2, 256>>>(pC, pFTh, pFTl, 512, i * 128);
        Xh = pFTh + (size_t)i * 128;
        Xl = pFTl + (size_t)i * 128;
        lda = 512;
    }
    gemm_bf16<<<g2, 256>>>(pFTh, pFTl, 512, 512, pOWh, pOWl, 512, pC, 128, nullptr);
    writeout_kernel<<<dim3(Npts / 32, 4, 24), 256>>>(out, big_off);
    if (has_mean) meanout_kernel<<<384, 256>>>(out, big_off, mean_off);
}

// round 9
// speedup vs baseline: 1.0145x; 1.0145x over previous
#include <cuda_runtime.h>
#include <cuda_bf16.h>
#include <math.h>
#include <float.h>
#include <stdint.h>

// ---------------- problem constants ----------------
#define Bsz   8
#define Npts  2048
#define Kn    16
#define Hc    128
#define Lc    4
#define CDc   128
#define Jtot  (Bsz * Npts * 3)
#define NBlk  (Bsz * Npts)
#define EPSf  1e-12f

typedef __nv_bfloat16 bf16;

// ---------------- scratch ----------------
__device__ int   g_idx[NBlk * Kn];
__device__ float g_M3[Hc * 3];
__device__ bf16  g_UKh[Lc * 256 * 128];
__device__ bf16  g_UKl[Lc * 256 * 128];
__device__ bf16  g_GWh[Lc * 256 * 256];
__device__ bf16  g_GWl[Lc * 256 * 256];
__device__ bf16  g_OWh[128 * 512];
__device__ bf16  g_OWl[128 * 512];
__device__ bf16  g_X0h[Jtot * 128];
__device__ bf16  g_X0l[Jtot * 128];
__device__ bf16  g_X2h[Jtot * 128];
__device__ bf16  g_X2l[Jtot * 128];
__device__ bf16  g_FTh[Jtot * 512];
__device__ bf16  g_FTl[Jtot * 512];
__device__ float g_C[Jtot * 256];
__device__ float g_gmean[Bsz * 3 * Hc];
__device__ float g_bias[24 * 256];

// ---------------- helpers ----------------
__device__ __forceinline__ void split2(float v, bf16& h, bf16& l) {
    h = __float2bfloat16(v);
    l = __float2bfloat16(v - __bfloat162float(h));
}

__device__ __forceinline__ uint32_t smem_u32(const void* p) {
    uint32_t r;
    asm("{ .reg .u64 t; cvta.to.shared.u64 t, %1; cvt.u32.u64 %0, t; }"
        : "=r"(r) : "l"(p));
    return r;
}

__device__ __forceinline__ void cpasync16(uint32_t dst, const void* src) {
    asm volatile("cp.async.cg.shared.global [%0], [%1], 16;" :: "r"(dst), "l"(src));
}
__device__ __forceinline__ void cpcommit() {
    asm volatile("cp.async.commit_group;" ::: "memory");
}
template <int N> __device__ __forceinline__ void cpwait() {
    asm volatile("cp.async.wait_group %0;" :: "n"(N) : "memory");
}

__device__ __forceinline__ void ldsm_x4(uint32_t& r0, uint32_t& r1,
                                        uint32_t& r2, uint32_t& r3, uint32_t addr) {
    asm volatile("ldmatrix.sync.aligned.m8n8.x4.shared.b16 {%0,%1,%2,%3}, [%4];"
                 : "=r"(r0), "=r"(r1), "=r"(r2), "=r"(r3) : "r"(addr));
}
__device__ __forceinline__ void ldsm_x2(uint32_t& r0, uint32_t& r1, uint32_t addr) {
    asm volatile("ldmatrix.sync.aligned.m8n8.x2.shared.b16 {%0,%1}, [%2];"
                 : "=r"(r0), "=r"(r1) : "r"(addr));
}
__device__ __forceinline__ void mma16816(float* d, const uint32_t* a, const uint32_t* b) {
    asm volatile("mma.sync.aligned.m16n8k16.row.col.f32.bf16.bf16.f32 "
                 "{%0,%1,%2,%3}, {%4,%5,%6,%7}, {%8,%9}, {%0,%1,%2,%3};"
                 : "+f"(d[0]), "+f"(d[1]), "+f"(d[2]), "+f"(d[3])
                 : "r"(a[0]), "r"(a[1]), "r"(a[2]), "r"(a[3]),
                   "r"(b[0]), "r"(b[1]));
}

// ---------------- prep: fused+stacked+split weights ----------------
__global__ void prep_kernel(const float* __restrict__ W_in,
                            const float* __restrict__ Wd_in,
                            const float* __restrict__ Ws,
                            const float* __restrict__ Wds,
                            const float* __restrict__ Gs,
                            const float* __restrict__ Gds,
                            const float* __restrict__ W_out) {
    int t = blockIdx.x * blockDim.x + threadIdx.x;
    const int N3  = Hc * 3;
    const int NUK = Lc * 256 * 128;
    const int NGW = Lc * 256 * 256;
    const int NOW = 128 * 512;
    if (t < N3) {
        int o = t / 3, i = t % 3;
        float s = 0.f;
        #pragma unroll 8
        for (int c = 0; c < Hc; c++) s += Wd_in[o * Hc + c] * W_in[c * 3 + i];
        g_M3[t] = s;
    } else if (t < N3 + NUK) {
        int r = t - N3;
        int l = r >> 15;
        int o = (r >> 7) & 255;
        int c = r & 127;
        float v;
        if (o < 128) {
            v = Ws[l * Hc * Hc + o * Hc + c];
        } else {
            const float* wd = Wds + l * Hc * Hc + (o - 128) * Hc;
            const float* w  = Ws  + l * Hc * Hc;
            float s = 0.f;
            #pragma unroll 8
            for (int cc = 0; cc < Hc; cc++) s += wd[cc] * w[cc * Hc + c];
            v = s;
        }
        split2(v, g_UKh[r], g_UKl[r]);
    } else if (t < N3 + NUK + NGW) {
        int r = t - N3 - NUK;
        int l = r >> 16;
        int o = (r >> 8) & 255;
        int c = r & 255;
        float v;
        if (o < 128) {
            v = Gs[l * Hc * 2 * Hc + o * 2 * Hc + c];
        } else {
            const float* gd = Gds + l * Hc * Hc + (o - 128) * Hc;
            const float* g  = Gs  + l * Hc * 2 * Hc;
            float s = 0.f;
            #pragma unroll 8
            for (int cc = 0; cc < Hc; cc++) s += gd[cc] * g[cc * 2 * Hc + c];
            v = s;
        }
        split2(v, g_GWh[r], g_GWl[r]);
    } else if (t < N3 + NUK + NGW + NOW) {
        int r = t - N3 - NUK - NGW;
        split2(W_out[r], g_OWh[r], g_OWl[r]);
    }
}

// ---------------- kNN ----------------
__global__ void knn_kernel(const float* __restrict__ x) {
    __shared__ float4 spts[Npts];
    int b = blockIdx.x >> 3;
    int chunk = blockIdx.x & 7;
    const float* xb = x + b * 3 * Npts;
    for (int i = threadIdx.x; i < Npts; i += 256) {
        float px = xb[i], py = xb[Npts + i], pz = xb[2 * Npts + i];
        spts[i] = make_float4(px, py, pz, px * px + py * py + pz * pz);
    }
    __syncthreads();
    int q = chunk * 256 + threadIdx.x;
    float4 Q = spts[q];
    float bd[Kn]; int bi[Kn];
    #pragma unroll
    for (int t = 0; t < Kn; t++) { bd[t] = FLT_MAX; bi[t] = 0; }
    float worst = FLT_MAX; int wslot = 0;
    for (int m = 0; m < Npts; m++) {
        float4 P = spts[m];
        float d2 = Q.w + P.w - 2.f * (Q.x * P.x + Q.y * P.y + Q.z * P.z);
        if (d2 < worst) {
            #pragma unroll
            for (int t = 0; t < Kn; t++) if (t == wslot) { bd[t] = d2; bi[t] = m; }
            worst = bd[0]; wslot = 0;
            #pragma unroll
            for (int t = 1; t < Kn; t++) if (bd[t] > worst) { worst = bd[t]; wslot = t; }
        }
    }
    int base = (b * Npts + q) * Kn;
    #pragma unroll
    for (int t = 0; t < Kn; t++) g_idx[base + t] = bi[t];
}

// ---------------- fused edge stage ----------------
__global__ void stage2_kernel(const float* __restrict__ x,
                              const float* __restrict__ W_in) {
    __shared__ float3 snbr[Kn];
    __shared__ float swk[4][Kn];
    int bn = blockIdx.x;
    int b = bn >> 11, n = bn & 2047;
    int c = threadIdx.x;
    int wid = c >> 5, lane = c & 31;
    const float* xb = x + b * 3 * Npts;
    float xnx = xb[n], xny = xb[Npts + n], xnz = xb[2 * Npts + n];
    float xl = sqrtf(xnx * xnx + xny * xny + xnz * xnz);
    float xinv = 1.f / fmaxf(xl, EPSf);
    float dxx = xnx * xinv, dxy = xny * xinv, dxz = xnz * xinv;
    if (c < Kn) {
        int m = g_idx[bn * Kn + c];
        snbr[c] = make_float3(xb[m], xb[Npts + m], xb[2 * Npts + m]);
    }
    __syncthreads();
    float w0 = W_in[c * 3 + 0], w1 = W_in[c * 3 + 1], w2 = W_in[c * 3 + 2];
    float m0 = g_M3[c * 3 + 0], m1 = g_M3[c * 3 + 1], m2 = g_M3[c * 3 + 2];
    float sumk[Kn];
    #pragma unroll
    for (int k = 0; k < Kn; k++) {
        float3 p = snbr[k];
        float c0x = dxy * p.z - dxz * p.y;
        float c0y = dxz * p.x - dxx * p.z;
        float c0z = dxx * p.y - dxy * p.x;
        float e1x = p.x - xnx, e1y = p.y - xny, e1z = p.z - xnz;
        float ux = w0 * c0x + w1 * e1x + w2 * xnx;
        float uy = w0 * c0y + w1 * e1y + w2 * xny;
        float uz = w0 * c0z + w1 * e1z + w2 * xnz;
        sumk[k] = ux * ux + uy * uy + uz * uz;
    }
    #pragma unroll
    for (int o = 16; o > 0; o >>= 1)
        #pragma unroll
        for (int k = 0; k < Kn; k++)
            sumk[k] += __shfl_xor_sync(0xffffffffu, sumk[k], o);
    if (lane == 0) {
        #pragma unroll
        for (int k = 0; k < Kn; k++) swk[wid][k] = sumk[k];
    }
    __syncthreads();
    float ax = 0.f, ay = 0.f, az = 0.f;
    #pragma unroll
    for (int k = 0; k < Kn; k++) {
        float tot = swk[0][k] + swk[1][k] + swk[2][k] + swk[3][k];
        float3 p = snbr[k];
        float c0x = dxy * p.z - dxz * p.y;
        float c0y = dxz * p.x - dxx * p.z;
        float c0z = dxx * p.y - dxy * p.x;
        float e1x = p.x - xnx, e1y = p.y - xny, e1z = p.z - xnz;
        float ux = w0 * c0x + w1 * e1x + w2 * xnx;
        float uy = w0 * c0y + w1 * e1y + w2 * xny;
        float uz = w0 * c0z + w1 * e1z + w2 * xnz;
        float kx = m0 * c0x + m1 * e1x + m2 * xnx;
        float ky = m0 * c0y + m1 * e1y + m2 * xny;
        float kz = m0 * c0z + m1 * e1z + m2 * xnz;
        float s = 1.f / fmaxf(sqrtf(tot), EPSf);
        float kl = sqrtf(kx * kx + ky * ky + kz * kz);
        float ki = 1.f / fmaxf(kl, EPSf);
        kx *= ki; ky *= ki; kz *= ki;
        float dot = s * (ux * kx + uy * ky + uz * kz);
        float neg = fminf(dot, 0.f);
        ax += s * ux - neg * kx;
        ay += s * uy - neg * ky;
        az += s * uz - neg * kz;
    }
    const float invK = 1.f / (float)Kn;
    int j0 = bn * 3;
    split2(ax * invK, g_X0h[(size_t)(j0 + 0) * Hc + c], g_X0l[(size_t)(j0 + 0) * Hc + c]);
    split2(ay * invK, g_X0h[(size_t)(j0 + 1) * Hc + c], g_X0l[(size_t)(j0 + 1) * Hc + c]);
    split2(az * invK, g_X0h[(size_t)(j0 + 2) * Hc + c], g_X0l[(size_t)(j0 + 2) * Hc + c]);
}

// ---------------- bf16x3 mma.sync GEMM: BM=128 BN=128, 3-stage cp.async ------
// C[j][n] = sum_c A[j,c]*W[n,c] (+ bias); K' = 3*Cin, BK=32.
// dyn smem: As[3][128*40] then Bs[3][128*40] bf16 = 61440 B.
__global__ __launch_bounds__(256, 2)
void gemm_bf16(const bf16* __restrict__ Ah, const bf16* __restrict__ Al, int lda, int Cin,
               const bf16* __restrict__ Wh, const bf16* __restrict__ Wl, int ldw,
               float* __restrict__ C, int ldc, const float* __restrict__ bias) {
    extern __shared__ __align__(16) bf16 smem[];
    int tid = threadIdx.x, lane = tid & 31, wid = tid >> 5;
    int warpM = wid >> 2, warpN = wid & 3;
    int jBase = blockIdx.x * 128;
    int nBase = blockIdx.y * 128;
    float acc[4][4][4];
    #pragma unroll
    for (int mt = 0; mt < 4; mt++)
        #pragma unroll
        for (int nt = 0; nt < 4; nt++)
            #pragma unroll
            for (int e = 0; e < 4; e++) acc[mt][nt][e] = 0.f;

    const int nIter = (3 * Cin) >> 5;
    const int ar = tid >> 1;
    const int ac = (tid & 1) * 2;
    uint32_t sA0 = smem_u32(smem);            // 3 A bufs @ 10240 B each
    uint32_t sB0 = sA0 + 30720;               // 3 B bufs @ 10240 B each

    #define LOAD_SLAB(IT, BUF)                                                     \
    do {                                                                           \
        int k0 = (IT) << 5;                                                        \
        int seg = k0 / Cin;                                                        \
        int kin = k0 - seg * Cin;                                                  \
        const bf16* Ap = (seg == 1) ? Al : Ah;                                     \
        const bf16* Bp = (seg == 2) ? Wl : Wh;                                     \
        uint32_t adst = sA0 + (BUF) * 10240 + (ar * 40 + ac * 8) * 2;              \
        uint32_t bdst = sB0 + (BUF) * 10240 + (ar * 40 + ac * 8) * 2;              \
        cpasync16(adst,      Ap + (size_t)(jBase + ar) * lda + kin + ac * 8);      \
        cpasync16(adst + 16, Ap + (size_t)(jBase + ar) * lda + kin + ac * 8 + 8);  \
        cpasync16(bdst,      Bp + (size_t)(nBase + ar) * ldw + kin + ac * 8);      \
        cpasync16(bdst + 16, Bp + (size_t)(nBase + ar) * ldw + kin + ac * 8 + 8);  \
    } while (0)

    LOAD_SLAB(0, 0);
    cpcommit();
    LOAD_SLAB(1, 1);
    cpcommit();

    int cur = 0;
    for (int it = 0; it < nIter; it++) {
        if (it == nIter - 1) cpwait<0>(); else cpwait<1>();
        __syncthreads();
        if (it + 2 < nIter) {
            int nbuf = cur + 2; if (nbuf >= 3) nbuf -= 3;
            LOAD_SLAB(it + 2, nbuf);
            cpcommit();
        }
        uint32_t sA = sA0 + cur * 10240;
        uint32_t sB = sB0 + cur * 10240;
        #pragma unroll
        for (int s = 0; s < 2; s++) {
            uint32_t afr[4][4];
            uint32_t bfr[4][2];
            #pragma unroll
            for (int mt = 0; mt < 4; mt++) {
                uint32_t addrA = sA + ((warpM * 64 + mt * 16 + (lane & 15)) * 40) * 2
                               + s * 32 + ((lane >> 4) << 4);
                ldsm_x4(afr[mt][0], afr[mt][1], afr[mt][2], afr[mt][3], addrA);
            }
            #pragma unroll
            for (int nt = 0; nt < 4; nt++) {
                uint32_t addrB = sB + ((warpN * 32 + nt * 8 + (lane & 7)) * 40) * 2
                               + s * 32 + (((lane >> 3) & 1) << 4);
                ldsm_x2(bfr[nt][0], bfr[nt][1], addrB);
            }
            #pragma unroll
            for (int mt = 0; mt < 4; mt++)
                #pragma unroll
                for (int nt = 0; nt < 4; nt++)
                    mma16816(acc[mt][nt], afr[mt], bfr[nt]);
        }
        if (++cur >= 3) cur = 0;
    }
    #undef LOAD_SLAB

    #pragma unroll
    for (int mt = 0; mt < 4; mt++) {
        int m = jBase + warpM * 64 + mt * 16 + (lane >> 2);
        int bd0 = (m / 6144) * 3 + (m % 3);
        int m8 = m + 8;
        int bd1 = (m8 / 6144) * 3 + (m8 % 3);
        #pragma unroll
        for (int nt = 0; nt < 4; nt++) {
            int n = nBase + warpN * 32 + nt * 8 + (lane & 3) * 2;
            float b00 = 0.f, b01 = 0.f, b10 = 0.f, b11 = 0.f;
            if (bias) {
                b00 = bias[bd0 * 256 + n];     b01 = bias[bd0 * 256 + n + 1];
                b10 = bias[bd1 * 256 + n];     b11 = bias[bd1 * 256 + n + 1];
            }
            *(float2*)&C[(size_t)m * ldc + n] =
                make_float2(acc[mt][nt][0] + b00, acc[mt][nt][1] + b01);
            *(float2*)&C[(size_t)m8 * ldc + n] =
                make_float2(acc[mt][nt][2] + b10, acc[mt][nt][3] + b11);
        }
    }
}
#define GEMM_SMEM 61440

// ---------------- vec_lna pointwise epilogue (2 bn per block) ----------------
__global__ __launch_bounds__(256)
void pointwise_kernel(const float* __restrict__ Cbuf,
                      bf16* __restrict__ dstH, bf16* __restrict__ dstL,
                      int ldd, int off) {
    __shared__ float sred[2][4];
    int half = threadIdx.x >> 7;
    int c = threadIdx.x & 127;
    int wih = (threadIdx.x >> 5) & 3;
    int lane = threadIdx.x & 31;
    int bn = blockIdx.x * 2 + half;
    int j0 = bn * 3;
    float ux = Cbuf[(size_t)(j0 + 0) * 256 + c];
    float uy = Cbuf[(size_t)(j0 + 1) * 256 + c];
    float uz = Cbuf[(size_t)(j0 + 2) * 256 + c];
    float kx = Cbuf[(size_t)(j0 + 0) * 256 + 128 + c];
    float ky = Cbuf[(size_t)(j0 + 1) * 256 + 128 + c];
    float kz = Cbuf[(size_t)(j0 + 2) * 256 + 128 + c];
    float v = ux * ux + uy * uy + uz * uz;
    #pragma unroll
    for (int o = 16; o > 0; o >>= 1) v += __shfl_xor_sync(0xffffffffu, v, o);
    if (lane == 0) sred[half][wih] = v;
    __syncthreads();
    float tot = sred[half][0] + sred[half][1] + sred[half][2] + sred[half][3];
    float s = 1.f / fmaxf(sqrtf(tot), EPSf);
    float kl = sqrtf(kx * kx + ky * ky + kz * kz);
    float ki = 1.f / fmaxf(kl, EPSf);
    kx *= ki; ky *= ki; kz *= ki;
    float dot = s * (ux * kx + uy * ky + uz * kz);
    float neg = fminf(dot, 0.f);
    split2(s * ux - neg * kx, dstH[(size_t)(j0 + 0) * ldd + off + c], dstL[(size_t)(j0 + 0) * ldd + off + c]);
    split2(s * uy - neg * ky, dstH[(size_t)(j0 + 1) * ldd + off + c], dstL[(size_t)(j0 + 1) * ldd + off + c]);
    split2(s * uz - neg * kz, dstH[(size_t)(j0 + 2) * ldd + off + c], dstL[(size_t)(j0 + 2) * ldd + off + c]);
}

// ---------------- fused mean-over-N + g-half bias ----------------
__global__ __launch_bounds__(1024)
void meanN_bias_kernel(const bf16* __restrict__ GWh, const bf16* __restrict__ GWl) {
    __shared__ float part[8][128];
    __shared__ float gm[128];
    int bd = blockIdx.x;
    int b = bd / 3, d = bd % 3;
    int c = threadIdx.x & 127;
    int slab = threadIdx.x >> 7;
    size_t base = ((size_t)(b * Npts + slab * 256) * 3 + d) * 128 + c;
    float s = 0.f;
    #pragma unroll 8
    for (int n = 0; n < 256; n++) {
        size_t a = base + (size_t)n * 384;
        s += __bfloat162float(g_X2h[a]) + __bfloat162float(g_X2l[a]);
    }
    part[slab][c] = s;
    __syncthreads();
    if (threadIdx.x < 128) {
        float t = 0.f;
        #pragma unroll
        for (int p = 0; p < 8; p++) t += part[p][c];
        g_gmean[bd * Hc + c] = t;
        gm[c] = t * (1.f / (float)Npts);
    }
    __syncthreads();
    if (threadIdx.x < 256) {
        int o = threadIdx.x;
        const bf16* rh = GWh + (size_t)o * 256 + 128;
        const bf16* rl = GWl + (size_t)o * 256 + 128;
        float acc = 0.f;
        #pragma unroll 8
        for (int cc = 0; cc < 128; cc++)
            acc += (__bfloat162float(rh[cc]) + __bfloat162float(rl[cc])) * gm[cc];
        g_bias[bd * 256 + o] = acc;
    }
}

// ---------------- coalesced tiled-transpose writeout ----------------
__global__ __launch_bounds__(256)
void writeout_kernel(float* __restrict__ out, int big_off) {
    __shared__ float tile[32][33];
    int tx = threadIdx.x & 31;
    int ty = threadIdx.x >> 5;
    int n0 = blockIdx.x * 32;
    int o0 = blockIdx.y * 32;
    int bd = blockIdx.z;
    int b = bd / 3, d = bd % 3;
    #pragma unroll
    for (int i = 0; i < 4; i++) {
        int n = n0 + ty + i * 8;
        tile[ty + i * 8][tx] = g_C[(((size_t)(b * Npts + n)) * 3 + d) * 128 + o0 + tx];
    }
    __syncthreads();
    #pragma unroll
    for (int i = 0; i < 4; i++) {
        int o = o0 + ty + i * 8;
        out[big_off + (((size_t)(b * 128 + o)) * 3 + d) * Npts + n0 + tx] = tile[tx][ty + i * 8];
    }
}

__global__ void meanout_kernel(float* __restrict__ out, int big_off, int mean_off) {
    int w = blockIdx.x * 8 + (threadIdx.x >> 5);
    int lane = threadIdx.x & 31;
    const float* base = out + big_off + (size_t)w * Npts;
    float s = 0.f;
    #pragma unroll 8
    for (int i = lane; i < Npts; i += 32) s += base[i];
    #pragma unroll
    for (int o = 16; o > 0; o >>= 1) s += __shfl_xor_sync(0xffffffffu, s, o);
    if (lane == 0) out[mean_off + w] = s * (1.f / (float)Npts);
}

// ---------------- host launcher ----------------
extern "C" void kernel_launch(void* const* d_in, const int* in_sizes, int n_in,
                              void* d_out, int out_size) {
    const float* x     = (const float*)d_in[0];
    const float* W_in  = (const float*)d_in[1];
    const float* Wd_in = (const float*)d_in[2];
    const float* Ws    = (const float*)d_in[3];
    const float* Wds   = (const float*)d_in[4];
    const float* Gs    = (const float*)d_in[5];
    const float* Gds   = (const float*)d_in[6];
    const float* W_out = (const float*)d_in[7];
    float* out = (float*)d_out;

    float *pC, *pBias;
    bf16 *pX0h, *pX0l, *pX2h, *pX2l, *pFTh, *pFTl, *pUKh, *pUKl, *pGWh, *pGWl, *pOWh, *pOWl;
    cudaGetSymbolAddress((void**)&pC, g_C);
    cudaGetSymbolAddress((void**)&pBias, g_bias);
    cudaGetSymbolAddress((void**)&pX0h, g_X0h);
    cudaGetSymbolAddress((void**)&pX0l, g_X0l);
    cudaGetSymbolAddress((void**)&pX2h, g_X2h);
    cudaGetSymbolAddress((void**)&pX2l, g_X2l);
    cudaGetSymbolAddress((void**)&pFTh, g_FTh);
    cudaGetSymbolAddress((void**)&pFTl, g_FTl);
    cudaGetSymbolAddress((void**)&pUKh, g_UKh);
    cudaGetSymbolAddress((void**)&pUKl, g_UKl);
    cudaGetSymbolAddress((void**)&pGWh, g_GWh);
    cudaGetSymbolAddress((void**)&pGWl, g_GWl);
    cudaGetSymbolAddress((void**)&pOWh, g_OWh);
    cudaGetSymbolAddress((void**)&pOWl, g_OWl);

    cudaFuncSetAttribute(gemm_bf16, cudaFuncAttributeMaxDynamicSharedMemorySize,
                         GEMM_SMEM);

    int mean_off = 0, big_off = 0;
    bool has_mean = true;
    const int BIG = Bsz * CDc * 3 * Npts;
    const int MEAN = Bsz * CDc * 3;
    if (out_size >= BIG + MEAN) { mean_off = 0; big_off = MEAN; }
    else { big_off = 0; has_mean = false; }

    const int prepTot = 384 + Lc * 256 * 128 + Lc * 256 * 256 + 128 * 512;
    prep_kernel<<<(prepTot + 255) / 256, 256>>>(W_in, Wd_in, Ws, Wds, Gs, Gds, W_out);
    knn_kernel<<<Bsz * 8, 256>>>(x);
    stage2_kernel<<<NBlk, 128>>>(x, W_in);

    const bf16* Xh = pX0h;
    const bf16* Xl = pX0l;
    int lda = Hc;
    dim3 g2(Jtot / 128, 2), g1(Jtot / 128, 1);
    for (int i = 0; i < Lc; i++) {
        gemm_bf16<<<g2, 256, GEMM_SMEM>>>(Xh, Xl, lda, 128,
                               pUKh + (size_t)i * 256 * 128, pUKl + (size_t)i * 256 * 128, 128,
                               pC, 256, nullptr);
        pointwise_kernel<<<NBlk / 2, 256>>>(pC, pX2h, pX2l, 128, 0);
        meanN_bias_kernel<<<24, 1024>>>(pGWh + (size_t)i * 256 * 256,
                                        pGWl + (size_t)i * 256 * 256);
        gemm_bf16<<<g2, 256, GEMM_SMEM>>>(pX2h, pX2l, 128, 128,
                               pGWh + (size_t)i * 256 * 256, pGWl + (size_t)i * 256 * 256, 256,
                               pC, 256, pBias);
        pointwise_kernel<<<NBlk / 2, 256>>>(pC, pFTh, pFTl, 512, i * 128);
        Xh = pFTh + (size_t)i * 128;
        Xl = pFTl + (size_t)i * 128;
        lda = 512;
    }
    gemm_bf16<<<g1, 256, GEMM_SMEM>>>(pFTh, pFTl, 512, 512, pOWh, pOWl, 512,
                                      pC, 128, nullptr);
    writeout_kernel<<<dim3(Npts / 32, 4, 24), 256>>>(out, big_off);
    if (has_mean) meanout_kernel<<<384, 256>>>(out, big_off, mean_off);
}